// round 6
// baseline (speedup 1.0000x reference)
#include <cuda_runtime.h>
#include <math.h>

#define BB 2048
#define TT 16
#define RR 2048
#define TPB 256
#define NPAIR 15

// Cross-kernel scratch (zero-init at load; prep/stream reset what they own).
__device__ float        g_w[NPAIR];   // per-step weight: 0.2/(R*max(cnt,1)*max(ns,1))
__device__ float        g_class;      // class loss (fully computed by prep)
__device__ float        g_total;      // smooth accumulation (reset by last block)
__device__ unsigned int g_done;       // election counter (reset by last block)

__device__ __forceinline__ float log_sigmoid(float x) {
    return fminf(x, 0.f) - log1pf(__expf(-fabsf(x)));
}

__device__ __forceinline__ float pen1(float a, float b) {
    float d = fabsf(a - b);
    float e = fmaxf(d - 0.2f, 0.f);
    return e * e;
}

// ---------------------------------------------------------------------------
// Prep: counts, ns, weights, class loss. One block; deterministic each call.
// ---------------------------------------------------------------------------
__global__ __launch_bounds__(1024)
void prep_kernel(const float* __restrict__ pred,
                 const int*   __restrict__ tgt,
                 const int*   __restrict__ vmask)
{
    const int tid  = threadIdx.x;
    const int lane = tid & 31;
    const int wid  = tid >> 5;

    __shared__ float s_cnt[NPAIR];
    __shared__ float s_bce[32];
    __shared__ float s_vms[32];
    __shared__ float s_ns;

    if (tid < NPAIR) s_cnt[tid] = 0.f;
    __syncthreads();

    // ---- pair-valid counts: each thread handles 2 b-rows ----
    float lc[NPAIR];
#pragma unroll
    for (int t = 0; t < NPAIR; t++) lc[t] = 0.f;
#pragma unroll
    for (int rep = 0; rep < 2; rep++) {
        int b = tid + rep * 1024;
        int vm[TT];
#pragma unroll
        for (int t = 0; t < TT; t++) vm[t] = vmask[b * TT + t];
#pragma unroll
        for (int t = 0; t < NPAIR; t++)
            if (vm[t] != 0 && vm[t + 1] != 0) lc[t] += 1.f;
    }
#pragma unroll
    for (int t = 0; t < NPAIR; t++) {
        float v = lc[t];
#pragma unroll
        for (int o = 16; o; o >>= 1) v += __shfl_xor_sync(0xffffffffu, v, o);
        if (lane == 0) atomicAdd(&s_cnt[t], v);
    }

    // ---- BCE-with-logits (pos_weight=2) and vm sum ----
    float bs = 0.f, vs = 0.f;
    for (int idx = tid; idx < BB * TT; idx += 1024) {
        float v = (float)vmask[idx];
        float y = (float)tgt[idx];
        float p = pred[idx];
        float bce = -(2.f * y * log_sigmoid(p) + (1.f - y) * log_sigmoid(-p));
        bs += bce * v;
        vs += v;
    }
#pragma unroll
    for (int o = 16; o; o >>= 1) {
        bs += __shfl_xor_sync(0xffffffffu, bs, o);
        vs += __shfl_xor_sync(0xffffffffu, vs, o);
    }
    if (lane == 0) { s_bce[wid] = bs; s_vms[wid] = vs; }
    __syncthreads();

    if (tid == 0) {
        float tb = 0.f, tv = 0.f;
#pragma unroll
        for (int w = 0; w < 32; w++) { tb += s_bce[w]; tv += s_vms[w]; }
        g_class = tb / fmaxf(tv, 1e-8f);

        int ns = 0;
#pragma unroll
        for (int t = 0; t < NPAIR; t++) if (s_cnt[t] > 0.f) ns++;
        s_ns = (float)(ns > 0 ? ns : 1);
    }
    __syncthreads();

    if (tid < NPAIR) {
        g_w[tid] = 0.2f / ((float)RR * fmaxf(s_cnt[tid], 1.f) * s_ns);
    }
}

// ---------------------------------------------------------------------------
// Stream: 268MB single pass; one accumulator per thread; tiny epilogue.
// ---------------------------------------------------------------------------
__global__ __launch_bounds__(TPB)
void stream_kernel(const float* __restrict__ rs,
                   const int*   __restrict__ vmask,
                   float*       __restrict__ out)
{
    const int b    = blockIdx.x;
    const int tid  = threadIdx.x;
    const int lane = tid & 31;
    const int wid  = tid >> 5;

    __shared__ float s_w[NPAIR];
    __shared__ float warp_acc[TPB / 32];
    __shared__ bool  s_last;

    if (tid < NPAIR) {
        int v0 = vmask[b * TT + tid];
        int v1 = vmask[b * TT + tid + 1];
        s_w[tid] = (v0 != 0 && v1 != 0) ? g_w[tid] : 0.f;
    }
    __syncthreads();

    // each thread owns 8 r columns (2 float4); full unroll over t
    const float4* base = (const float4*)rs + (size_t)b * TT * (RR / 4);
    float4 p0 = base[tid];
    float4 p1 = base[tid + TPB];

    float acc = 0.f;
#pragma unroll
    for (int t = 1; t < TT; t++) {
        float4 c0 = base[t * (RR / 4) + tid];
        float4 c1 = base[t * (RR / 4) + tid + TPB];
        float a = 0.f;
        a += pen1(c0.x, p0.x);  a += pen1(c0.y, p0.y);
        a += pen1(c0.z, p0.z);  a += pen1(c0.w, p0.w);
        a += pen1(c1.x, p1.x);  a += pen1(c1.y, p1.y);
        a += pen1(c1.z, p1.z);  a += pen1(c1.w, p1.w);
        acc = fmaf(a, s_w[t - 1], acc);
        p0 = c0; p1 = c1;
    }

    // single block reduction + one atomic
#pragma unroll
    for (int o = 16; o; o >>= 1) acc += __shfl_xor_sync(0xffffffffu, acc, o);
    if (lane == 0) warp_acc[wid] = acc;
    __syncthreads();

    if (tid == 0) {
        float s = 0.f;
#pragma unroll
        for (int w = 0; w < TPB / 32; w++) s += warp_acc[w];
        atomicAdd(&g_total, s);
        __threadfence();
        unsigned prev = atomicAdd(&g_done, 1u);
        s_last = (prev == (unsigned)(BB - 1));
    }
    __syncthreads();

    if (s_last && tid == 0) {
        out[0] = g_class + g_total;   // weights already carry 0.2 & normalizers
        g_total = 0.f;                // reset for next graph replay
        g_done  = 0u;
    }
}

extern "C" void kernel_launch(void* const* d_in, const int* in_sizes, int n_in,
                              void* d_out, int out_size)
{
    const float* pred  = (const float*)d_in[0];  // [B,T,1]
    const float* rs    = (const float*)d_in[1];  // [B,T,R,1]
    const int*   tgt   = (const int*)d_in[2];    // [B,T]
    const int*   vmask = (const int*)d_in[3];    // [B,T]
    float*       out   = (float*)d_out;

    prep_kernel<<<1, 1024>>>(pred, tgt, vmask);
    stream_kernel<<<BB, TPB>>>(rs, vmask, out);
}

// round 7
// speedup vs baseline: 1.5924x; 1.5924x over previous
#include <cuda_runtime.h>
#include <math.h>

#define BB 2048
#define TT 16
#define RR 2048
#define TPB 256
#define NPAIR 15

// 32 accumulator slots: [0..14] step sums, [15..29] step counts,
// [30] bce*vm sum, [31] vm sum. Zero at module load; the elected last
// block re-zeroes after reading, so graph replays always start clean.
__device__ float        g_acc[32];
__device__ unsigned int g_done;   // completion counter, reset by last block

__device__ __forceinline__ float log_sigmoid(float x) {
    return fminf(x, 0.f) - log1pf(__expf(-fabsf(x)));
}

__device__ __forceinline__ float pen1(float a, float b) {
    float d = fabsf(a - b);
    float e = fmaxf(d - 0.2f, 0.f);
    return e * e;
}

__global__ __launch_bounds__(TPB)
void fused_loss_kernel(const float* __restrict__ pred,
                       const float* __restrict__ rs,
                       const int*   __restrict__ tgt,
                       const int*   __restrict__ vmask,
                       float*       __restrict__ out)
{
    const int b   = blockIdx.x;
    const int tid = threadIdx.x;

    __shared__ float s_vm[TT];
    __shared__ float s_bce[TT];
    __shared__ float red[NPAIR][TPB / 32];
    __shared__ bool  s_last;

    // ---- tiny BCE part: threads 0..15 handle the 16 timesteps of this b ----
    if (tid < TT) {
        int idx   = b * TT + tid;
        float v   = (float)vmask[idx];
        float y   = (float)tgt[idx];
        float p   = pred[idx];
        float bce = -(2.f * y * log_sigmoid(p) + (1.f - y) * log_sigmoid(-p));
        s_vm[tid]  = v;
        s_bce[tid] = bce * v;
    }

    // ---- streaming smoothness: each thread owns 8 r columns (2 float4) ----
    const float4* base = (const float4*)rs + (size_t)b * TT * (RR / 4);
    float4 p0 = __ldcs(&base[tid]);
    float4 p1 = __ldcs(&base[tid + TPB]);

    float acc[NPAIR];
#pragma unroll
    for (int t = 0; t < NPAIR; t++) acc[t] = 0.f;

#pragma unroll
    for (int t = 1; t < TT; t++) {
        float4 c0 = __ldcs(&base[t * (RR / 4) + tid]);
        float4 c1 = __ldcs(&base[t * (RR / 4) + tid + TPB]);
        float a = 0.f;
        a += pen1(c0.x, p0.x);  a += pen1(c0.y, p0.y);
        a += pen1(c0.z, p0.z);  a += pen1(c0.w, p0.w);
        a += pen1(c1.x, p1.x);  a += pen1(c1.y, p1.y);
        a += pen1(c1.z, p1.z);  a += pen1(c1.w, p1.w);
        acc[t - 1] = a;
        p0 = c0; p1 = c1;
    }

    // ---- block reduction of the 15 per-t sums ----
    const int lane = tid & 31, wid = tid >> 5;
#pragma unroll
    for (int t = 0; t < NPAIR; t++) {
        float v = acc[t];
#pragma unroll
        for (int o = 16; o; o >>= 1) v += __shfl_xor_sync(0xffffffffu, v, o);
        if (lane == 0) red[t][wid] = v;
    }
    __syncthreads();

    // ---- global accumulation via atomics (REDG; hidden under DRAM stream) ----
    if (tid < NPAIR) {
        float pv = (s_vm[tid] > 0.5f && s_vm[tid + 1] > 0.5f) ? 1.f : 0.f;
        if (pv > 0.f) {
            float s = 0.f;
#pragma unroll
            for (int w = 0; w < TPB / 32; w++) s += red[tid][w];
            atomicAdd(&g_acc[tid], s);
            atomicAdd(&g_acc[NPAIR + tid], 1.f);
        }
    }
    if (tid == 0) {
        float bs = 0.f, vs = 0.f;
#pragma unroll
        for (int t = 0; t < TT; t++) { bs += s_bce[t]; vs += s_vm[t]; }
        atomicAdd(&g_acc[30], bs);
        atomicAdd(&g_acc[31], vs);
    }
    __syncthreads();

    // ---- last-block-done election ----
    if (tid == 0) {
        __threadfence();  // make this block's atomics visible before signaling
        unsigned prev = atomicAdd(&g_done, 1u);
        s_last = (prev == (unsigned)(BB - 1));
    }
    __syncthreads();

    if (s_last && tid < 32) {
        float v = g_acc[tid];
        // reset for the next graph replay (value already consumed)
        g_acc[tid] = 0.f;
        if (tid == 0) g_done = 0u;

        float ssum = 0.f;
        int ns = 0;
#pragma unroll
        for (int t = 0; t < NPAIR; t++) {
            float s = __shfl_sync(0xffffffffu, v, t);
            float c = __shfl_sync(0xffffffffu, v, NPAIR + t);
            if (c > 0.f) ns++;
            ssum += s / ((float)RR * fmaxf(c, 1.f));
        }
        float bs = __shfl_sync(0xffffffffu, v, 30);
        float vs = __shfl_sync(0xffffffffu, v, 31);
        if (tid == 0) {
            float smooth = (ns > 0) ? (ssum / (float)ns) : 0.f;
            float cls    = bs / fmaxf(vs, 1e-8f);
            out[0] = cls + 0.2f * smooth;
        }
    }
}

extern "C" void kernel_launch(void* const* d_in, const int* in_sizes, int n_in,
                              void* d_out, int out_size)
{
    const float* pred  = (const float*)d_in[0];  // [B,T,1]
    const float* rs    = (const float*)d_in[1];  // [B,T,R,1]
    const int*   tgt   = (const int*)d_in[2];    // [B,T]
    const int*   vmask = (const int*)d_in[3];    // [B,T]
    float*       out   = (float*)d_out;

    fused_loss_kernel<<<BB, TPB>>>(pred, rs, tgt, vmask, out);
}